// round 3
// baseline (speedup 1.0000x reference)
#include <cuda_runtime.h>
#include <math.h>

// Problem constants
#define D_MODEL 1024
#define NHEAD   16
#define DKH     64
#define S_LEN   2048
#define BATCH   4
#define ROWS    (BATCH * S_LEN)   // 8192

// Scratch (static device globals: allocation-free per harness rules)
__device__ float g_Q[ROWS * D_MODEL];
__device__ float g_K[ROWS * D_MODEL];
__device__ float g_V[ROWS * D_MODEL];
__device__ float g_ctx[ROWS * D_MODEL];

// ---------------------------------------------------------------------------
// GEMM core: 64x64 block tile, BK=16, 256 threads, 4x4 per thread.
// C[m,n] = sum_k A[m,k] * W[n,k]   (both operands k-contiguous)
// ---------------------------------------------------------------------------
#define BM 64
#define BN 64
#define BKK 16
#define GP 68   // pitch: 68*4B = 272B, multiple of 16 -> aligned float4 reads

__device__ __forceinline__ void gemm_core(
    const float* __restrict__ A, const float* __restrict__ W,
    int m0, int n0, float (&acc)[4][4],
    float (*As)[GP], float (*Ws)[GP])
{
    const int K = D_MODEL;
    int tid = threadIdx.x;
    int tx = tid & 15, ty = tid >> 4;
    int row = tid >> 2, kc = tid & 3;
    const float* Ap = A + (size_t)(m0 + row) * K + kc * 4;
    const float* Wp = W + (size_t)(n0 + row) * K + kc * 4;
    float4 av = *(const float4*)Ap;
    float4 wv = *(const float4*)Wp;
    for (int k0 = 0; k0 < K; k0 += BKK) {
        __syncthreads();
        As[kc*4+0][row] = av.x; As[kc*4+1][row] = av.y;
        As[kc*4+2][row] = av.z; As[kc*4+3][row] = av.w;
        Ws[kc*4+0][row] = wv.x; Ws[kc*4+1][row] = wv.y;
        Ws[kc*4+2][row] = wv.z; Ws[kc*4+3][row] = wv.w;
        __syncthreads();
        if (k0 + BKK < K) {   // prefetch next tile while computing
            av = *(const float4*)(Ap + k0 + BKK);
            wv = *(const float4*)(Wp + k0 + BKK);
        }
        #pragma unroll
        for (int kk = 0; kk < BKK; kk++) {
            float4 a = *(const float4*)&As[kk][ty * 4];
            float4 w = *(const float4*)&Ws[kk][tx * 4];
            acc[0][0] += a.x*w.x; acc[0][1] += a.x*w.y; acc[0][2] += a.x*w.z; acc[0][3] += a.x*w.w;
            acc[1][0] += a.y*w.x; acc[1][1] += a.y*w.y; acc[1][2] += a.y*w.z; acc[1][3] += a.y*w.w;
            acc[2][0] += a.z*w.x; acc[2][1] += a.z*w.y; acc[2][2] += a.z*w.z; acc[2][3] += a.z*w.w;
            acc[3][0] += a.w*w.x; acc[3][1] += a.w*w.y; acc[3][2] += a.w*w.z; acc[3][3] += a.w*w.w;
        }
    }
}

// ---------------------------------------------------------------------------
// Kernel 1: fused QKV projection. grid = (16 n-tiles [= head], 128 m-tiles, 3 [q/k/v])
// Epilogue writes straight into head-split layout [B, H, S, dk].
// ---------------------------------------------------------------------------
__global__ void __launch_bounds__(256)
qkv_proj_kernel(const float* __restrict__ q, const float* __restrict__ k_,
                const float* __restrict__ v,
                const float* __restrict__ Wq, const float* __restrict__ bq,
                const float* __restrict__ Wk, const float* __restrict__ bk,
                const float* __restrict__ Wv, const float* __restrict__ bv)
{
    __shared__ float As[BKK][GP];
    __shared__ float Ws[BKK][GP];
    const float* A; const float* W; const float* bias; float* O;
    int z = blockIdx.z;
    if (z == 0)      { A = q;  W = Wq; bias = bq; O = g_Q; }
    else if (z == 1) { A = k_; W = Wk; bias = bk; O = g_K; }
    else             { A = v;  W = Wv; bias = bv; O = g_V; }

    int m0 = blockIdx.y * BM;
    int h  = blockIdx.x;           // n0 = h * 64
    float acc[4][4] = {};
    gemm_core(A, W, m0, h * BN, acc, As, Ws);

    int tx = threadIdx.x & 15, ty = threadIdx.x >> 4;
    float4 bb = *(const float4*)(bias + h * 64 + tx * 4);
    #pragma unroll
    for (int i = 0; i < 4; i++) {
        int m = m0 + ty * 4 + i;
        int b = m >> 11;           // / 2048
        int s = m & 2047;
        float4 o;
        o.x = acc[i][0] + bb.x; o.y = acc[i][1] + bb.y;
        o.z = acc[i][2] + bb.z; o.w = acc[i][3] + bb.w;
        *(float4*)(O + ((size_t)(b * NHEAD + h) * S_LEN + s) * DKH + tx * 4) = o;
    }
}

// ---------------------------------------------------------------------------
// Kernel 2: flash-style attention. grid = (32 q-tiles, 64 b*h), 256 threads.
// Loader: each thread covers 16 floats (4 float4s) of the 64x64 K/V chunk:
// row lr = tid>>2, column base lc0 = (tid&3)*16, j-subchunks of 4.
// (256 threads x 16 floats = 4096 = full 64x64 chunk coverage.)
// ---------------------------------------------------------------------------
#define BQ  64
#define BKV 64

__global__ void __launch_bounds__(256)
attn_kernel()
{
    __shared__ float Qs[DKH * BQ];     // [d][q]
    __shared__ float KVs[BKV * DKH];   // K: [d][kv]  then  V: [kv][d]
    __shared__ float Ps[BQ * BKV];     // [q][kv]

    int tid = threadIdx.x, tx = tid & 15, ty = tid >> 4;
    int bh = blockIdx.y;
    int q0 = blockIdx.x * BQ;
    const float* Qb = g_Q + (size_t)bh * S_LEN * DKH;
    const float* Kb = g_K + (size_t)bh * S_LEN * DKH;
    const float* Vb = g_V + (size_t)bh * S_LEN * DKH;

    // Load Q tile, transposed into Qs[d][q]  (1024 float4s = full 64x64)
    #pragma unroll
    for (int s4 = 0; s4 < 4; s4++) {
        int sl = tid * 4 + s4;
        int r = sl >> 4, d4 = (sl & 15) << 2;
        float4 t = *(const float4*)(Qb + (size_t)(q0 + r) * DKH + d4);
        Qs[(d4+0)*BQ + r] = t.x; Qs[(d4+1)*BQ + r] = t.y;
        Qs[(d4+2)*BQ + r] = t.z; Qs[(d4+3)*BQ + r] = t.w;
    }

    float m_run[4], l_run[4], acc[4][4];
    #pragma unroll
    for (int i = 0; i < 4; i++) {
        m_run[i] = -INFINITY; l_run[i] = 0.f;
        #pragma unroll
        for (int j = 0; j < 4; j++) acc[i][j] = 0.f;
    }

    const int lr  = tid >> 2;          // 0..63: kv-row within chunk
    const int lc0 = (tid & 3) << 4;    // 0,16,32,48: dim base

    // Prefetch first K chunk: 4 float4s per thread -> full 64x64 coverage
    float4 kreg[4];
    #pragma unroll
    for (int j = 0; j < 4; j++)
        kreg[j] = *(const float4*)(Kb + (size_t)lr * DKH + lc0 + j * 4);

    const float SCALE = 0.125f;   // 1/sqrt(64)

    for (int c = 0; c < S_LEN / BKV; c++) {
        __syncthreads();   // prev PV reads of KVs/Ps complete
        // store K chunk transposed: Ks[d][kv]
        #pragma unroll
        for (int j = 0; j < 4; j++) {
            int d = lc0 + j * 4;
            KVs[(d+0)*BKV + lr] = kreg[j].x;
            KVs[(d+1)*BKV + lr] = kreg[j].y;
            KVs[(d+2)*BKV + lr] = kreg[j].z;
            KVs[(d+3)*BKV + lr] = kreg[j].w;
        }
        __syncthreads();

        // prefetch V chunk (latency overlaps S-compute)
        float4 vreg[4];
        #pragma unroll
        for (int j = 0; j < 4; j++)
            vreg[j] = *(const float4*)(Vb + (size_t)(c * BKV + lr) * DKH + lc0 + j * 4);

        // S = scale * Q K^T  (64x64, 4x4 per thread)
        float sc[4][4] = {};
        #pragma unroll 8
        for (int d = 0; d < DKH; d++) {
            float4 a = *(const float4*)&Qs[d * BQ + ty * 4];
            float4 b = *(const float4*)&KVs[d * BKV + tx * 4];
            sc[0][0] += a.x*b.x; sc[0][1] += a.x*b.y; sc[0][2] += a.x*b.z; sc[0][3] += a.x*b.w;
            sc[1][0] += a.y*b.x; sc[1][1] += a.y*b.y; sc[1][2] += a.y*b.z; sc[1][3] += a.y*b.w;
            sc[2][0] += a.z*b.x; sc[2][1] += a.z*b.y; sc[2][2] += a.z*b.z; sc[2][3] += a.z*b.w;
            sc[3][0] += a.w*b.x; sc[3][1] += a.w*b.y; sc[3][2] += a.w*b.z; sc[3][3] += a.w*b.w;
        }

        // Online softmax per row (reduction over the 16 tx lanes of each half-warp)
        #pragma unroll
        for (int i = 0; i < 4; i++) {
            #pragma unroll
            for (int j = 0; j < 4; j++) sc[i][j] *= SCALE;
            float mc = fmaxf(fmaxf(sc[i][0], sc[i][1]), fmaxf(sc[i][2], sc[i][3]));
            #pragma unroll
            for (int o = 8; o > 0; o >>= 1)
                mc = fmaxf(mc, __shfl_xor_sync(0xffffffffu, mc, o));
            float mnew = fmaxf(m_run[i], mc);
            float corr = __expf(m_run[i] - mnew);
            m_run[i] = mnew;
            float ps = 0.f;
            #pragma unroll
            for (int j = 0; j < 4; j++) {
                float p = __expf(sc[i][j] - mnew);
                sc[i][j] = p; ps += p;
            }
            #pragma unroll
            for (int o = 8; o > 0; o >>= 1)
                ps += __shfl_xor_sync(0xffffffffu, ps, o);
            l_run[i] = l_run[i] * corr + ps;
            acc[i][0] *= corr; acc[i][1] *= corr; acc[i][2] *= corr; acc[i][3] *= corr;
        }

        __syncthreads();   // all warps done reading K region of KVs
        // write P tile, store V chunk (natural [kv][d])
        #pragma unroll
        for (int i = 0; i < 4; i++) {
            float4 p; p.x = sc[i][0]; p.y = sc[i][1]; p.z = sc[i][2]; p.w = sc[i][3];
            *(float4*)&Ps[(ty*4 + i) * BKV + tx * 4] = p;
        }
        #pragma unroll
        for (int j = 0; j < 4; j++)
            *(float4*)&KVs[lr * DKH + lc0 + j * 4] = vreg[j];
        // prefetch next K chunk (latency overlaps PV-compute)
        if (c + 1 < S_LEN / BKV) {
            #pragma unroll
            for (int j = 0; j < 4; j++)
                kreg[j] = *(const float4*)(Kb + (size_t)((c + 1) * BKV + lr) * DKH + lc0 + j * 4);
        }
        __syncthreads();

        // O += P @ V
        #pragma unroll 4
        for (int kv = 0; kv < BKV; kv += 4) {
            float p[4][4], vv[4][4];
            #pragma unroll
            for (int i = 0; i < 4; i++) {
                float4 t = *(const float4*)&Ps[(ty*4 + i) * BKV + kv];
                p[i][0] = t.x; p[i][1] = t.y; p[i][2] = t.z; p[i][3] = t.w;
            }
            #pragma unroll
            for (int r = 0; r < 4; r++) {
                float4 t = *(const float4*)&KVs[(kv + r) * DKH + tx * 4];
                vv[r][0] = t.x; vv[r][1] = t.y; vv[r][2] = t.z; vv[r][3] = t.w;
            }
            #pragma unroll
            for (int i = 0; i < 4; i++)
                #pragma unroll
                for (int r = 0; r < 4; r++) {
                    acc[i][0] += p[i][r] * vv[r][0];
                    acc[i][1] += p[i][r] * vv[r][1];
                    acc[i][2] += p[i][r] * vv[r][2];
                    acc[i][3] += p[i][r] * vv[r][3];
                }
        }
    }

    // Normalize and store into [B, S, H*dk] (= merged-head) layout
    int b = bh >> 4, h = bh & 15;
    #pragma unroll
    for (int i = 0; i < 4; i++) {
        float inv = 1.0f / l_run[i];
        int s = q0 + ty * 4 + i;
        float4 o;
        o.x = acc[i][0] * inv; o.y = acc[i][1] * inv;
        o.z = acc[i][2] * inv; o.w = acc[i][3] * inv;
        *(float4*)(g_ctx + (size_t)(b * S_LEN + s) * D_MODEL + h * DKH + tx * 4) = o;
    }
}

// ---------------------------------------------------------------------------
// Kernel 3: output projection  out = ctx @ Wo^T + bo
// ---------------------------------------------------------------------------
__global__ void __launch_bounds__(256)
out_proj_kernel(const float* __restrict__ Wo, const float* __restrict__ bo,
                float* __restrict__ out)
{
    __shared__ float As[BKK][GP];
    __shared__ float Ws[BKK][GP];
    int m0 = blockIdx.y * BM;
    int n0 = blockIdx.x * BN;
    float acc[4][4] = {};
    gemm_core(g_ctx, Wo, m0, n0, acc, As, Ws);

    int tx = threadIdx.x & 15, ty = threadIdx.x >> 4;
    float4 bb = *(const float4*)(bo + n0 + tx * 4);
    #pragma unroll
    for (int i = 0; i < 4; i++) {
        int m = m0 + ty * 4 + i;
        float4 o;
        o.x = acc[i][0] + bb.x; o.y = acc[i][1] + bb.y;
        o.z = acc[i][2] + bb.z; o.w = acc[i][3] + bb.w;
        *(float4*)(out + (size_t)m * D_MODEL + n0 + tx * 4) = o;
    }
}

// ---------------------------------------------------------------------------
// Launch. Input order (metadata): q,k,v,Wq,bq,Wk,bk,Wv,bv,Wo,bo
// ---------------------------------------------------------------------------
extern "C" void kernel_launch(void* const* d_in, const int* in_sizes, int n_in,
                              void* d_out, int out_size)
{
    const float* q  = (const float*)d_in[0];
    const float* k  = (const float*)d_in[1];
    const float* v  = (const float*)d_in[2];
    const float* Wq = (const float*)d_in[3];
    const float* bq = (const float*)d_in[4];
    const float* Wk = (const float*)d_in[5];
    const float* bk = (const float*)d_in[6];
    const float* Wv = (const float*)d_in[7];
    const float* bv = (const float*)d_in[8];
    const float* Wo = (const float*)d_in[9];
    const float* bo = (const float*)d_in[10];
    float* out = (float*)d_out;

    dim3 blk(256);
    qkv_proj_kernel<<<dim3(D_MODEL / BN, ROWS / BM, 3), blk>>>(
        q, k, v, Wq, bq, Wk, bk, Wv, bv);
    attn_kernel<<<dim3(S_LEN / BQ, BATCH * NHEAD), blk>>>();
    out_proj_kernel<<<dim3(D_MODEL / BN, ROWS / BM), blk>>>(Wo, bo, out);
}

// round 5
// speedup vs baseline: 1.2077x; 1.2077x over previous
#include <cuda_runtime.h>
#include <math.h>

// Problem constants
#define D_MODEL 1024
#define NHEAD   16
#define DKH     64
#define S_LEN   2048
#define BATCH   4
#define ROWS    (BATCH * S_LEN)   // 8192

// Scratch (static device globals: allocation-free per harness rules)
__device__ float g_Q[ROWS * D_MODEL];
__device__ float g_K[ROWS * D_MODEL];
__device__ float g_V[ROWS * D_MODEL];
__device__ float g_ctx[ROWS * D_MODEL];

// ---------------------------------------------------------------------------
// GEMM core: 128x128 block tile, BK=16, 256 threads, 8x8 per thread.
// C[m,n] = sum_k A[m,k] * W[n,k]   (both operands k-contiguous)
// Smem [k][m]/[k][n], pitch 132 (132*4B = 16-multiple; breaks the k<->k+8
// bank alias so the paired-STS store pattern is conflict-free).
// Each thread loads k columns {kc..kc+3, kc+8..kc+11}, kc = (tid&1)*4.
// ---------------------------------------------------------------------------
#define BM 128
#define BN 128
#define BKK 16
#define GP 132

__device__ __forceinline__ void gemm_core(
    const float* __restrict__ A, const float* __restrict__ W,
    int m0, int n0, float (&acc)[8][8],
    float (*As)[GP], float (*Ws)[GP])
{
    const int K = D_MODEL;
    int tid = threadIdx.x;
    int tx = tid & 15, ty = tid >> 4;
    int row = tid >> 1;            // 0..127
    int kc  = (tid & 1) * 4;       // 0 or 4; second float4 at kc+8
    const float* Ap = A + (size_t)(m0 + row) * K + kc;
    const float* Wp = W + (size_t)(n0 + row) * K + kc;
    float4 av0 = *(const float4*)(Ap);
    float4 av1 = *(const float4*)(Ap + 8);
    float4 wv0 = *(const float4*)(Wp);
    float4 wv1 = *(const float4*)(Wp + 8);
    for (int k0 = 0; k0 < K; k0 += BKK) {
        __syncthreads();
        As[kc+0][row] = av0.x; As[kc+1][row] = av0.y;
        As[kc+2][row] = av0.z; As[kc+3][row] = av0.w;
        As[kc+8][row] = av1.x; As[kc+9][row] = av1.y;
        As[kc+10][row] = av1.z; As[kc+11][row] = av1.w;
        Ws[kc+0][row] = wv0.x; Ws[kc+1][row] = wv0.y;
        Ws[kc+2][row] = wv0.z; Ws[kc+3][row] = wv0.w;
        Ws[kc+8][row] = wv1.x; Ws[kc+9][row] = wv1.y;
        Ws[kc+10][row] = wv1.z; Ws[kc+11][row] = wv1.w;
        __syncthreads();
        if (k0 + BKK < K) {   // prefetch next tile while computing
            av0 = *(const float4*)(Ap + k0 + BKK);
            av1 = *(const float4*)(Ap + k0 + BKK + 8);
            wv0 = *(const float4*)(Wp + k0 + BKK);
            wv1 = *(const float4*)(Wp + k0 + BKK + 8);
        }
        #pragma unroll
        for (int kk = 0; kk < BKK; kk++) {
            float4 a0 = *(const float4*)&As[kk][ty * 8];
            float4 a1 = *(const float4*)&As[kk][ty * 8 + 4];
            float4 b0 = *(const float4*)&Ws[kk][tx * 8];
            float4 b1 = *(const float4*)&Ws[kk][tx * 8 + 4];
            float a[8] = {a0.x,a0.y,a0.z,a0.w,a1.x,a1.y,a1.z,a1.w};
            float b[8] = {b0.x,b0.y,b0.z,b0.w,b1.x,b1.y,b1.z,b1.w};
            #pragma unroll
            for (int i = 0; i < 8; i++)
                #pragma unroll
                for (int j = 0; j < 8; j++)
                    acc[i][j] += a[i] * b[j];
        }
    }
}

// ---------------------------------------------------------------------------
// Kernel 1: fused QKV projection. grid = (8 n-tiles, 64 m-tiles, 3 [q/k/v])
// Epilogue writes straight into head-split layout [B, H, S, dk]; a thread's
// 8 columns (8-aligned) never cross a 64-wide head boundary.
// ---------------------------------------------------------------------------
__global__ void __launch_bounds__(256, 2)
qkv_proj_kernel(const float* __restrict__ q, const float* __restrict__ k_,
                const float* __restrict__ v,
                const float* __restrict__ Wq, const float* __restrict__ bq,
                const float* __restrict__ Wk, const float* __restrict__ bk,
                const float* __restrict__ Wv, const float* __restrict__ bv)
{
    __shared__ float As[BKK][GP];
    __shared__ float Ws[BKK][GP];
    const float* A; const float* W; const float* bias; float* O;
    int z = blockIdx.z;
    if (z == 0)      { A = q;  W = Wq; bias = bq; O = g_Q; }
    else if (z == 1) { A = k_; W = Wk; bias = bk; O = g_K; }
    else             { A = v;  W = Wv; bias = bv; O = g_V; }

    int m0 = blockIdx.y * BM;
    int n0 = blockIdx.x * BN;
    float acc[8][8] = {};
    gemm_core(A, W, m0, n0, acc, As, Ws);

    int tx = threadIdx.x & 15, ty = threadIdx.x >> 4;
    int n = n0 + tx * 8;
    int h = n >> 6;            // head
    int off = n & 63;          // offset within head
    float4 bb0 = *(const float4*)(bias + n);
    float4 bb1 = *(const float4*)(bias + n + 4);
    #pragma unroll
    for (int i = 0; i < 8; i++) {
        int m = m0 + ty * 8 + i;
        int b = m >> 11;           // / 2048
        int s = m & 2047;
        float* dst = O + ((size_t)(b * NHEAD + h) * S_LEN + s) * DKH + off;
        float4 o0, o1;
        o0.x = acc[i][0] + bb0.x; o0.y = acc[i][1] + bb0.y;
        o0.z = acc[i][2] + bb0.z; o0.w = acc[i][3] + bb0.w;
        o1.x = acc[i][4] + bb1.x; o1.y = acc[i][5] + bb1.y;
        o1.z = acc[i][6] + bb1.z; o1.w = acc[i][7] + bb1.w;
        *(float4*)(dst)     = o0;
        *(float4*)(dst + 4) = o1;
    }
}

// ---------------------------------------------------------------------------
// Kernel 2: flash-style attention. grid = (16 q-tiles, 64 b*h), 256 threads.
// BQ=128 rows per CTA, BKV=64 per chunk; thread tile 8 rows x 4 cols.
// Dynamic smem 80 KB: Qs[d][q] 64x128, KVs (K^T then V) 64x64, Ps 128x64.
// ---------------------------------------------------------------------------
#define BQ  128
#define BKV 64
#define ATTN_SMEM ((DKH*BQ + BKV*DKH + BQ*BKV) * 4)   // 81920 bytes

__global__ void __launch_bounds__(256)
attn_kernel()
{
    extern __shared__ float sm[];
    float* Qs  = sm;                       // [d][q]  64 x 128
    float* KVs = sm + DKH * BQ;            // K: [d][kv] 64x64, then V: [kv][d]
    float* Ps  = sm + DKH * BQ + BKV * DKH; // [q][kv] 128 x 64

    int tid = threadIdx.x, tx = tid & 15, ty = tid >> 4;
    int bh = blockIdx.y;
    int q0 = blockIdx.x * BQ;
    const float* Qb = g_Q + (size_t)bh * S_LEN * DKH;
    const float* Kb = g_K + (size_t)bh * S_LEN * DKH;
    const float* Vb = g_V + (size_t)bh * S_LEN * DKH;

    // Load Q tile transposed into Qs[d][q]: 2048 float4s, 8 per thread
    #pragma unroll
    for (int s4 = 0; s4 < 8; s4++) {
        int sl = tid * 8 + s4;             // 0..2047
        int r  = sl >> 4;                  // 0..127
        int d4 = (sl & 15) << 2;           // 0..60
        float4 t = *(const float4*)(Qb + (size_t)(q0 + r) * DKH + d4);
        Qs[(d4+0)*BQ + r] = t.x; Qs[(d4+1)*BQ + r] = t.y;
        Qs[(d4+2)*BQ + r] = t.z; Qs[(d4+3)*BQ + r] = t.w;
    }

    float m_run[8], l_run[8], acc[8][4];
    #pragma unroll
    for (int i = 0; i < 8; i++) {
        m_run[i] = -INFINITY; l_run[i] = 0.f;
        #pragma unroll
        for (int j = 0; j < 4; j++) acc[i][j] = 0.f;
    }

    const int lr  = tid >> 2;          // 0..63: kv-row within chunk
    const int lc0 = (tid & 3) << 4;    // 0,16,32,48: dim base
    // Prefetch first K chunk: 4 float4s per thread = full 64x64 coverage
    float4 kreg[4];
    #pragma unroll
    for (int j = 0; j < 4; j++)
        kreg[j] = *(const float4*)(Kb + (size_t)lr * DKH + lc0 + j * 4);

    const float SCALE = 0.125f;        // 1/sqrt(64)

    for (int c = 0; c < S_LEN / BKV; c++) {
        __syncthreads();   // prev PV reads of KVs/Ps complete (also fences Q load)
        // store K chunk transposed: K^T[d][kv]
        #pragma unroll
        for (int j = 0; j < 4; j++) {
            int d = lc0 + j * 4;
            KVs[(d+0)*BKV + lr] = kreg[j].x;
            KVs[(d+1)*BKV + lr] = kreg[j].y;
            KVs[(d+2)*BKV + lr] = kreg[j].z;
            KVs[(d+3)*BKV + lr] = kreg[j].w;
        }
        __syncthreads();

        // prefetch V chunk (latency overlaps S-compute)
        float4 vreg[4];
        #pragma unroll
        for (int j = 0; j < 4; j++)
            vreg[j] = *(const float4*)(Vb + (size_t)(c * BKV + lr) * DKH + lc0 + j * 4);

        // S = Q K^T  (128x64 tile, 8x4 per thread)
        float sc[8][4] = {};
        #pragma unroll 8
        for (int d = 0; d < DKH; d++) {
            float4 a0 = *(const float4*)&Qs[d * BQ + ty * 8];
            float4 a1 = *(const float4*)&Qs[d * BQ + ty * 8 + 4];
            float4 b  = *(const float4*)&KVs[d * BKV + tx * 4];
            float a[8] = {a0.x,a0.y,a0.z,a0.w,a1.x,a1.y,a1.z,a1.w};
            #pragma unroll
            for (int i = 0; i < 8; i++) {
                sc[i][0] += a[i]*b.x; sc[i][1] += a[i]*b.y;
                sc[i][2] += a[i]*b.z; sc[i][3] += a[i]*b.w;
            }
        }

        // Online softmax per row (reduction over the 16 tx lanes per half-warp)
        #pragma unroll
        for (int i = 0; i < 8; i++) {
            #pragma unroll
            for (int j = 0; j < 4; j++) sc[i][j] *= SCALE;
            float mc = fmaxf(fmaxf(sc[i][0], sc[i][1]), fmaxf(sc[i][2], sc[i][3]));
            #pragma unroll
            for (int o = 8; o > 0; o >>= 1)
                mc = fmaxf(mc, __shfl_xor_sync(0xffffffffu, mc, o));
            float mnew = fmaxf(m_run[i], mc);
            float corr = __expf(m_run[i] - mnew);
            m_run[i] = mnew;
            float ps = 0.f;
            #pragma unroll
            for (int j = 0; j < 4; j++) {
                float p = __expf(sc[i][j] - mnew);
                sc[i][j] = p; ps += p;
            }
            #pragma unroll
            for (int o = 8; o > 0; o >>= 1)
                ps += __shfl_xor_sync(0xffffffffu, ps, o);
            l_run[i] = l_run[i] * corr + ps;
            acc[i][0] *= corr; acc[i][1] *= corr;
            acc[i][2] *= corr; acc[i][3] *= corr;
        }

        __syncthreads();   // all warps done reading K region of KVs
        // write P tile; store V chunk (natural [kv][d]); prefetch next K
        #pragma unroll
        for (int i = 0; i < 8; i++) {
            float4 p; p.x = sc[i][0]; p.y = sc[i][1]; p.z = sc[i][2]; p.w = sc[i][3];
            *(float4*)&Ps[(ty*8 + i) * BKV + tx * 4] = p;
        }
        #pragma unroll
        for (int j = 0; j < 4; j++)
            *(float4*)&KVs[lr * DKH + lc0 + j * 4] = vreg[j];
        if (c + 1 < S_LEN / BKV) {
            #pragma unroll
            for (int j = 0; j < 4; j++)
                kreg[j] = *(const float4*)(Kb + (size_t)((c + 1) * BKV + lr) * DKH + lc0 + j * 4);
        }
        __syncthreads();

        // O += P @ V   (p loaded per-row to keep register peak low)
        #pragma unroll 4
        for (int kv = 0; kv < BKV; kv += 4) {
            float vv[4][4];
            #pragma unroll
            for (int r = 0; r < 4; r++) {
                float4 t = *(const float4*)&KVs[(kv + r) * DKH + tx * 4];
                vv[r][0] = t.x; vv[r][1] = t.y; vv[r][2] = t.z; vv[r][3] = t.w;
            }
            #pragma unroll
            for (int i = 0; i < 8; i++) {
                float4 p = *(const float4*)&Ps[(ty*8 + i) * BKV + kv];
                float pr[4] = {p.x, p.y, p.z, p.w};
                #pragma unroll
                for (int r = 0; r < 4; r++) {
                    acc[i][0] += pr[r] * vv[r][0];
                    acc[i][1] += pr[r] * vv[r][1];
                    acc[i][2] += pr[r] * vv[r][2];
                    acc[i][3] += pr[r] * vv[r][3];
                }
            }
        }
    }

    // Normalize and store into [B, S, H*dk] (= merged-head) layout
    int b = bh >> 4, h = bh & 15;
    #pragma unroll
    for (int i = 0; i < 8; i++) {
        float inv = 1.0f / l_run[i];
        int s = q0 + ty * 8 + i;
        float4 o;
        o.x = acc[i][0] * inv; o.y = acc[i][1] * inv;
        o.z = acc[i][2] * inv; o.w = acc[i][3] * inv;
        *(float4*)(g_ctx + (size_t)(b * S_LEN + s) * D_MODEL + h * DKH + tx * 4) = o;
    }
}

// ---------------------------------------------------------------------------
// Kernel 3: output projection  out = ctx @ Wo^T + bo
// ---------------------------------------------------------------------------
__global__ void __launch_bounds__(256, 2)
out_proj_kernel(const float* __restrict__ Wo, const float* __restrict__ bo,
                float* __restrict__ out)
{
    __shared__ float As[BKK][GP];
    __shared__ float Ws[BKK][GP];
    int m0 = blockIdx.y * BM;
    int n0 = blockIdx.x * BN;
    float acc[8][8] = {};
    gemm_core(g_ctx, Wo, m0, n0, acc, As, Ws);

    int tx = threadIdx.x & 15, ty = threadIdx.x >> 4;
    int n = n0 + tx * 8;
    float4 bb0 = *(const float4*)(bo + n);
    float4 bb1 = *(const float4*)(bo + n + 4);
    #pragma unroll
    for (int i = 0; i < 8; i++) {
        int m = m0 + ty * 8 + i;
        float4 o0, o1;
        o0.x = acc[i][0] + bb0.x; o0.y = acc[i][1] + bb0.y;
        o0.z = acc[i][2] + bb0.z; o0.w = acc[i][3] + bb0.w;
        o1.x = acc[i][4] + bb1.x; o1.y = acc[i][5] + bb1.y;
        o1.z = acc[i][6] + bb1.z; o1.w = acc[i][7] + bb1.w;
        *(float4*)(out + (size_t)m * D_MODEL + n)     = o0;
        *(float4*)(out + (size_t)m * D_MODEL + n + 4) = o1;
    }
}

// ---------------------------------------------------------------------------
// Launch. Input order (metadata): q,k,v,Wq,bq,Wk,bk,Wv,bv,Wo,bo
// ---------------------------------------------------------------------------
extern "C" void kernel_launch(void* const* d_in, const int* in_sizes, int n_in,
                              void* d_out, int out_size)
{
    const float* q  = (const float*)d_in[0];
    const float* k  = (const float*)d_in[1];
    const float* v  = (const float*)d_in[2];
    const float* Wq = (const float*)d_in[3];
    const float* bq = (const float*)d_in[4];
    const float* Wk = (const float*)d_in[5];
    const float* bk = (const float*)d_in[6];
    const float* Wv = (const float*)d_in[7];
    const float* bv = (const float*)d_in[8];
    const float* Wo = (const float*)d_in[9];
    const float* bo = (const float*)d_in[10];
    float* out = (float*)d_out;

    // Idempotent, host-side, capture-safe: allow 80 KB dynamic smem for attn
    cudaFuncSetAttribute(attn_kernel,
                         cudaFuncAttributeMaxDynamicSharedMemorySize, ATTN_SMEM);

    dim3 blk(256);
    qkv_proj_kernel<<<dim3(D_MODEL / BN, ROWS / BM, 3), blk>>>(
        q, k, v, Wq, bq, Wk, bk, Wv, bv);
    attn_kernel<<<dim3(S_LEN / BQ, BATCH * NHEAD), blk, ATTN_SMEM>>>();
    out_proj_kernel<<<dim3(D_MODEL / BN, ROWS / BM), blk>>>(Wo, bo, out);
}

// round 7
// speedup vs baseline: 1.2832x; 1.0625x over previous
#include <cuda_runtime.h>
#include <math.h>

// Problem constants
#define D_MODEL 1024
#define NHEAD   16
#define DKH     64
#define S_LEN   2048
#define BATCH   4
#define ROWS    (BATCH * S_LEN)   // 8192

// Scratch (static device globals: allocation-free per harness rules)
__device__ float g_Q[ROWS * D_MODEL];
__device__ float g_K[ROWS * D_MODEL];
__device__ float g_V[ROWS * D_MODEL];
__device__ float g_ctx[ROWS * D_MODEL];

// ---------------------------------------------------------------------------
// GEMM core: 128x128 block tile, BK=16, 256 threads, 8x8 per thread.
// C[m,n] = sum_k A[m,k] * W[n,k]   (both operands k-contiguous)
//
// Ws stores n-columns PERMUTED: column n = 8t+j lands at p(n) = 4t + (j&3)
// + (j>=4)*64.  Thread tx then reads b0 = [tx*4], b1 = [64+tx*4]:
// quarter-warp lanes hit banks 0,4,...,28 (conflict-free), and those
// positions hold exactly columns {8tx..8tx+3} / {8tx+4..8tx+7}, so the
// accumulator -> output mapping is unchanged from the identity layout.
// As reads are ty-broadcast (conflict-free) and stay identity.
// ---------------------------------------------------------------------------
#define BM 128
#define BN 128
#define BKK 16
#define GP 132

__device__ __forceinline__ int wperm(int n) {   // b-side column permutation
    return ((n >> 3) << 2) + (n & 3) + ((n & 4) << 4);
}

__device__ __forceinline__ void gemm_core(
    const float* __restrict__ A, const float* __restrict__ W,
    int m0, int n0, float (&acc)[8][8],
    float (*As)[GP], float (*Ws)[GP])
{
    const int K = D_MODEL;
    int tid = threadIdx.x;
    int tx = tid & 15, ty = tid >> 4;
    int row = tid >> 1;            // 0..127
    int prow = wperm(row);         // permuted position for Ws stores
    int kc  = (tid & 1) * 4;       // 0 or 4; second float4 at kc+8
    const float* Ap = A + (size_t)(m0 + row) * K + kc;
    const float* Wp = W + (size_t)(n0 + row) * K + kc;
    float4 av0 = *(const float4*)(Ap);
    float4 av1 = *(const float4*)(Ap + 8);
    float4 wv0 = *(const float4*)(Wp);
    float4 wv1 = *(const float4*)(Wp + 8);
    for (int k0 = 0; k0 < K; k0 += BKK) {
        __syncthreads();
        As[kc+0][row] = av0.x; As[kc+1][row] = av0.y;
        As[kc+2][row] = av0.z; As[kc+3][row] = av0.w;
        As[kc+8][row] = av1.x; As[kc+9][row] = av1.y;
        As[kc+10][row] = av1.z; As[kc+11][row] = av1.w;
        Ws[kc+0][prow] = wv0.x; Ws[kc+1][prow] = wv0.y;
        Ws[kc+2][prow] = wv0.z; Ws[kc+3][prow] = wv0.w;
        Ws[kc+8][prow] = wv1.x; Ws[kc+9][prow] = wv1.y;
        Ws[kc+10][prow] = wv1.z; Ws[kc+11][prow] = wv1.w;
        __syncthreads();
        if (k0 + BKK < K) {   // prefetch next tile while computing
            av0 = *(const float4*)(Ap + k0 + BKK);
            av1 = *(const float4*)(Ap + k0 + BKK + 8);
            wv0 = *(const float4*)(Wp + k0 + BKK);
            wv1 = *(const float4*)(Wp + k0 + BKK + 8);
        }
        #pragma unroll
        for (int kk = 0; kk < BKK; kk++) {
            float4 a0 = *(const float4*)&As[kk][ty * 8];
            float4 a1 = *(const float4*)&As[kk][ty * 8 + 4];
            float4 b0 = *(const float4*)&Ws[kk][tx * 4];        // cols 8tx..8tx+3
            float4 b1 = *(const float4*)&Ws[kk][64 + tx * 4];   // cols 8tx+4..8tx+7
            float a[8] = {a0.x,a0.y,a0.z,a0.w,a1.x,a1.y,a1.z,a1.w};
            float b[8] = {b0.x,b0.y,b0.z,b0.w,b1.x,b1.y,b1.z,b1.w};
            #pragma unroll
            for (int i = 0; i < 8; i++)
                #pragma unroll
                for (int j = 0; j < 8; j++)
                    acc[i][j] += a[i] * b[j];
        }
    }
}

// ---------------------------------------------------------------------------
// Kernel 1: fused QKV projection. grid = (8 n-tiles, 64 m-tiles, 3 [q/k/v])
// Epilogue writes straight into head-split layout [B, H, S, dk]; a thread's
// 8 columns (8-aligned) never cross a 64-wide head boundary.
// ---------------------------------------------------------------------------
__global__ void __launch_bounds__(256, 2)
qkv_proj_kernel(const float* __restrict__ q, const float* __restrict__ k_,
                const float* __restrict__ v,
                const float* __restrict__ Wq, const float* __restrict__ bq,
                const float* __restrict__ Wk, const float* __restrict__ bk,
                const float* __restrict__ Wv, const float* __restrict__ bv)
{
    __shared__ float As[BKK][GP];
    __shared__ float Ws[BKK][GP];
    const float* A; const float* W; const float* bias; float* O;
    int z = blockIdx.z;
    if (z == 0)      { A = q;  W = Wq; bias = bq; O = g_Q; }
    else if (z == 1) { A = k_; W = Wk; bias = bk; O = g_K; }
    else             { A = v;  W = Wv; bias = bv; O = g_V; }

    int m0 = blockIdx.y * BM;
    int n0 = blockIdx.x * BN;
    float acc[8][8] = {};
    gemm_core(A, W, m0, n0, acc, As, Ws);

    int tx = threadIdx.x & 15, ty = threadIdx.x >> 4;
    int n = n0 + tx * 8;
    int h = n >> 6;            // head
    int off = n & 63;          // offset within head
    float4 bb0 = *(const float4*)(bias + n);
    float4 bb1 = *(const float4*)(bias + n + 4);
    #pragma unroll
    for (int i = 0; i < 8; i++) {
        int m = m0 + ty * 8 + i;
        int b = m >> 11;           // / 2048
        int s = m & 2047;
        float* dst = O + ((size_t)(b * NHEAD + h) * S_LEN + s) * DKH + off;
        float4 o0, o1;
        o0.x = acc[i][0] + bb0.x; o0.y = acc[i][1] + bb0.y;
        o0.z = acc[i][2] + bb0.z; o0.w = acc[i][3] + bb0.w;
        o1.x = acc[i][4] + bb1.x; o1.y = acc[i][5] + bb1.y;
        o1.z = acc[i][6] + bb1.z; o1.w = acc[i][7] + bb1.w;
        *(float4*)(dst)     = o0;
        *(float4*)(dst + 4) = o1;
    }
}

// ---------------------------------------------------------------------------
// Kernel 2: flash-style attention. grid = (16 q-tiles, 64 b*h), 256 threads.
// BQ=128 rows per CTA, BKV=64 per chunk; thread tile 8 rows x 4 cols.
// Dynamic smem 80 KB: Qs[d][q] 64x128, KVs (K^T then V) 64x64, Ps 128x64.
// Smem reads here are already conflict-free (tx*4 strides / ty broadcast).
// ---------------------------------------------------------------------------
#define BQ  128
#define BKV 64
#define ATTN_SMEM ((DKH*BQ + BKV*DKH + BQ*BKV) * 4)   // 81920 bytes

__global__ void __launch_bounds__(256)
attn_kernel()
{
    extern __shared__ float sm[];
    float* Qs  = sm;                       // [d][q]  64 x 128
    float* KVs = sm + DKH * BQ;            // K: [d][kv] 64x64, then V: [kv][d]
    float* Ps  = sm + DKH * BQ + BKV * DKH; // [q][kv] 128 x 64

    int tid = threadIdx.x, tx = tid & 15, ty = tid >> 4;
    int bh = blockIdx.y;
    int q0 = blockIdx.x * BQ;
    const float* Qb = g_Q + (size_t)bh * S_LEN * DKH;
    const float* Kb = g_K + (size_t)bh * S_LEN * DKH;
    const float* Vb = g_V + (size_t)bh * S_LEN * DKH;

    // Load Q tile transposed into Qs[d][q]: 2048 float4s, 8 per thread
    #pragma unroll
    for (int s4 = 0; s4 < 8; s4++) {
        int sl = tid * 8 + s4;             // 0..2047
        int r  = sl >> 4;                  // 0..127
        int d4 = (sl & 15) << 2;           // 0..60
        float4 t = *(const float4*)(Qb + (size_t)(q0 + r) * DKH + d4);
        Qs[(d4+0)*BQ + r] = t.x; Qs[(d4+1)*BQ + r] = t.y;
        Qs[(d4+2)*BQ + r] = t.z; Qs[(d4+3)*BQ + r] = t.w;
    }

    float m_run[8], l_run[8], acc[8][4];
    #pragma unroll
    for (int i = 0; i < 8; i++) {
        m_run[i] = -INFINITY; l_run[i] = 0.f;
        #pragma unroll
        for (int j = 0; j < 4; j++) acc[i][j] = 0.f;
    }

    const int lr  = tid >> 2;          // 0..63: kv-row within chunk
    const int lc0 = (tid & 3) << 4;    // 0,16,32,48: dim base
    // Prefetch first K chunk: 4 float4s per thread = full 64x64 coverage
    float4 kreg[4];
    #pragma unroll
    for (int j = 0; j < 4; j++)
        kreg[j] = *(const float4*)(Kb + (size_t)lr * DKH + lc0 + j * 4);

    const float SCALE = 0.125f;        // 1/sqrt(64)

    for (int c = 0; c < S_LEN / BKV; c++) {
        __syncthreads();   // prev PV reads of KVs/Ps complete (also fences Q load)
        // store K chunk transposed: K^T[d][kv]
        #pragma unroll
        for (int j = 0; j < 4; j++) {
            int d = lc0 + j * 4;
            KVs[(d+0)*BKV + lr] = kreg[j].x;
            KVs[(d+1)*BKV + lr] = kreg[j].y;
            KVs[(d+2)*BKV + lr] = kreg[j].z;
            KVs[(d+3)*BKV + lr] = kreg[j].w;
        }
        __syncthreads();

        // prefetch V chunk (latency overlaps S-compute)
        float4 vreg[4];
        #pragma unroll
        for (int j = 0; j < 4; j++)
            vreg[j] = *(const float4*)(Vb + (size_t)(c * BKV + lr) * DKH + lc0 + j * 4);

        // S = Q K^T  (128x64 tile, 8x4 per thread)
        float sc[8][4] = {};
        #pragma unroll 8
        for (int d = 0; d < DKH; d++) {
            float4 a0 = *(const float4*)&Qs[d * BQ + ty * 8];
            float4 a1 = *(const float4*)&Qs[d * BQ + ty * 8 + 4];
            float4 b  = *(const float4*)&KVs[d * BKV + tx * 4];
            float a[8] = {a0.x,a0.y,a0.z,a0.w,a1.x,a1.y,a1.z,a1.w};
            #pragma unroll
            for (int i = 0; i < 8; i++) {
                sc[i][0] += a[i]*b.x; sc[i][1] += a[i]*b.y;
                sc[i][2] += a[i]*b.z; sc[i][3] += a[i]*b.w;
            }
        }

        // Online softmax per row (reduction over the 16 tx lanes per half-warp)
        #pragma unroll
        for (int i = 0; i < 8; i++) {
            #pragma unroll
            for (int j = 0; j < 4; j++) sc[i][j] *= SCALE;
            float mc = fmaxf(fmaxf(sc[i][0], sc[i][1]), fmaxf(sc[i][2], sc[i][3]));
            #pragma unroll
            for (int o = 8; o > 0; o >>= 1)
                mc = fmaxf(mc, __shfl_xor_sync(0xffffffffu, mc, o));
            float mnew = fmaxf(m_run[i], mc);
            float corr = __expf(m_run[i] - mnew);
            m_run[i] = mnew;
            float ps = 0.f;
            #pragma unroll
            for (int j = 0; j < 4; j++) {
                float p = __expf(sc[i][j] - mnew);
                sc[i][j] = p; ps += p;
            }
            #pragma unroll
            for (int o = 8; o > 0; o >>= 1)
                ps += __shfl_xor_sync(0xffffffffu, ps, o);
            l_run[i] = l_run[i] * corr + ps;
            acc[i][0] *= corr; acc[i][1] *= corr;
            acc[i][2] *= corr; acc[i][3] *= corr;
        }

        __syncthreads();   // all warps done reading K region of KVs
        // write P tile; store V chunk (natural [kv][d]); prefetch next K
        #pragma unroll
        for (int i = 0; i < 8; i++) {
            float4 p; p.x = sc[i][0]; p.y = sc[i][1]; p.z = sc[i][2]; p.w = sc[i][3];
            *(float4*)&Ps[(ty*8 + i) * BKV + tx * 4] = p;
        }
        #pragma unroll
        for (int j = 0; j < 4; j++)
            *(float4*)&KVs[lr * DKH + lc0 + j * 4] = vreg[j];
        if (c + 1 < S_LEN / BKV) {
            #pragma unroll
            for (int j = 0; j < 4; j++)
                kreg[j] = *(const float4*)(Kb + (size_t)((c + 1) * BKV + lr) * DKH + lc0 + j * 4);
        }
        __syncthreads();

        // O += P @ V   (p loaded per-row to keep register peak low)
        #pragma unroll 4
        for (int kv = 0; kv < BKV; kv += 4) {
            float vv[4][4];
            #pragma unroll
            for (int r = 0; r < 4; r++) {
                float4 t = *(const float4*)&KVs[(kv + r) * DKH + tx * 4];
                vv[r][0] = t.x; vv[r][1] = t.y; vv[r][2] = t.z; vv[r][3] = t.w;
            }
            #pragma unroll
            for (int i = 0; i < 8; i++) {
                float4 p = *(const float4*)&Ps[(ty*8 + i) * BKV + kv];
                float pr[4] = {p.x, p.y, p.z, p.w};
                #pragma unroll
                for (int r = 0; r < 4; r++) {
                    acc[i][0] += pr[r] * vv[r][0];
                    acc[i][1] += pr[r] * vv[r][1];
                    acc[i][2] += pr[r] * vv[r][2];
                    acc[i][3] += pr[r] * vv[r][3];
                }
            }
        }
    }

    // Normalize and store into [B, S, H*dk] (= merged-head) layout
    int b = bh >> 4, h = bh & 15;
    #pragma unroll
    for (int i = 0; i < 8; i++) {
        float inv = 1.0f / l_run[i];
        int s = q0 + ty * 8 + i;
        float4 o;
        o.x = acc[i][0] * inv; o.y = acc[i][1] * inv;
        o.z = acc[i][2] * inv; o.w = acc[i][3] * inv;
        *(float4*)(g_ctx + (size_t)(b * S_LEN + s) * D_MODEL + h * DKH + tx * 4) = o;
    }
}

// ---------------------------------------------------------------------------
// Kernel 3: output projection  out = ctx @ Wo^T + bo
// ---------------------------------------------------------------------------
__global__ void __launch_bounds__(256, 2)
out_proj_kernel(const float* __restrict__ Wo, const float* __restrict__ bo,
                float* __restrict__ out)
{
    __shared__ float As[BKK][GP];
    __shared__ float Ws[BKK][GP];
    int m0 = blockIdx.y * BM;
    int n0 = blockIdx.x * BN;
    float acc[8][8] = {};
    gemm_core(g_ctx, Wo, m0, n0, acc, As, Ws);

    int tx = threadIdx.x & 15, ty = threadIdx.x >> 4;
    int n = n0 + tx * 8;
    float4 bb0 = *(const float4*)(bo + n);
    float4 bb1 = *(const float4*)(bo + n + 4);
    #pragma unroll
    for (int i = 0; i < 8; i++) {
        int m = m0 + ty * 8 + i;
        float4 o0, o1;
        o0.x = acc[i][0] + bb0.x; o0.y = acc[i][1] + bb0.y;
        o0.z = acc[i][2] + bb0.z; o0.w = acc[i][3] + bb0.w;
        o1.x = acc[i][4] + bb1.x; o1.y = acc[i][5] + bb1.y;
        o1.z = acc[i][6] + bb1.z; o1.w = acc[i][7] + bb1.w;
        *(float4*)(out + (size_t)m * D_MODEL + n)     = o0;
        *(float4*)(out + (size_t)m * D_MODEL + n + 4) = o1;
    }
}

// ---------------------------------------------------------------------------
// Launch. Input order (metadata): q,k,v,Wq,bq,Wk,bk,Wv,bv,Wo,bo
// ---------------------------------------------------------------------------
extern "C" void kernel_launch(void* const* d_in, const int* in_sizes, int n_in,
                              void* d_out, int out_size)
{
    const float* q  = (const float*)d_in[0];
    const float* k  = (const float*)d_in[1];
    const float* v  = (const float*)d_in[2];
    const float* Wq = (const float*)d_in[3];
    const float* bq = (const float*)d_in[4];
    const float* Wk = (const float*)d_in[5];
    const float* bk = (const float*)d_in[6];
    const float* Wv = (const float*)d_in[7];
    const float* bv = (const float*)d_in[8];
    const float* Wo = (const float*)d_in[9];
    const float* bo = (const float*)d_in[10];
    float* out = (float*)d_out;

    // Idempotent, host-side, capture-safe: allow 80 KB dynamic smem for attn
    cudaFuncSetAttribute(attn_kernel,
                         cudaFuncAttributeMaxDynamicSharedMemorySize, ATTN_SMEM);

    dim3 blk(256);
    qkv_proj_kernel<<<dim3(D_MODEL / BN, ROWS / BM, 3), blk>>>(
        q, k, v, Wq, bq, Wk, bk, Wv, bv);
    attn_kernel<<<dim3(S_LEN / BQ, BATCH * NHEAD), blk, ATTN_SMEM>>>();
    out_proj_kernel<<<dim3(D_MODEL / BN, ROWS / BM), blk>>>(Wo, bo, out);
}

// round 8
// speedup vs baseline: 1.4882x; 1.1598x over previous
#include <cuda_runtime.h>
#include <cuda_bf16.h>
#include <mma.h>
#include <math.h>

using namespace nvcuda;

// Problem constants
#define D_MODEL 1024
#define NHEAD   16
#define DKH     64
#define S_LEN   2048
#define BATCH   4
#define ROWS    (BATCH * S_LEN)   // 8192

// Scratch (static device globals: allocation-free per harness rules)
__device__ float g_Q[ROWS * D_MODEL];
__device__ float g_K[ROWS * D_MODEL];
__device__ float g_V[ROWS * D_MODEL];
__device__ float g_ctx[ROWS * D_MODEL];

// ---------------------------------------------------------------------------
// Projection GEMM via wmma bf16 split:  C = A @ W^T + bias
//   x = hi(x) + lo(x)  (two bf16);  x*y ~= xh*yh + xh*yl + xl*yh  (fp32 acc)
// CTA tile 128x128, K-chunk 32, 256 threads = 8 warps, warp tile 32x64
// (2 m-tiles x 4 n-tiles of m16n16k16).
// Smem planes [128][40] bf16 per operand per half (pitch 40: multiple of 8
// for wmma ldm).  Bias folded in by loading accumulator fragments from a
// replicated bias tile that shares (unions) the plane storage.
// ---------------------------------------------------------------------------
#define PBM 128
#define PBK 32
#define PP  40                      // bf16 plane pitch (elements)
#define PLANE_BYTES (PBM * PP * 2)  // 10240
#define PSM_BYTES   (4 * PLANE_BYTES)

typedef wmma::fragment<wmma::matrix_a, 16,16,16, __nv_bfloat16, wmma::row_major> FragA;
typedef wmma::fragment<wmma::matrix_b, 16,16,16, __nv_bfloat16, wmma::col_major> FragB;
typedef wmma::fragment<wmma::accumulator, 16,16,16, float> FragC;

__device__ __forceinline__ void split_store(__nv_bfloat16* hi, __nv_bfloat16* lo,
                                            int idx, float4 v)
{
    float f[4] = {v.x, v.y, v.z, v.w};
    __nv_bfloat16 h[4], l[4];
    #pragma unroll
    for (int e = 0; e < 4; e++) {
        h[e] = __float2bfloat16_rn(f[e]);
        l[e] = __float2bfloat16_rn(f[e] - __bfloat162float(h[e]));
    }
    // idx is even; 4-byte-aligned paired stores
    *reinterpret_cast<__nv_bfloat162*>(hi + idx)     = __nv_bfloat162(h[0], h[1]);
    *reinterpret_cast<__nv_bfloat162*>(hi + idx + 2) = __nv_bfloat162(h[2], h[3]);
    *reinterpret_cast<__nv_bfloat162*>(lo + idx)     = __nv_bfloat162(l[0], l[1]);
    *reinterpret_cast<__nv_bfloat162*>(lo + idx + 2) = __nv_bfloat162(l[2], l[3]);
}

__device__ __forceinline__ void proj_gemm_core(
    const float* __restrict__ A, const float* __restrict__ W,
    const float* __restrict__ bias, int m0, int n0,
    unsigned char* smem_raw, FragC (&acc)[2][4])
{
    __nv_bfloat16* Ahi = reinterpret_cast<__nv_bfloat16*>(smem_raw);
    __nv_bfloat16* Alo = reinterpret_cast<__nv_bfloat16*>(smem_raw + PLANE_BYTES);
    __nv_bfloat16* Bhi = reinterpret_cast<__nv_bfloat16*>(smem_raw + 2*PLANE_BYTES);
    __nv_bfloat16* Blo = reinterpret_cast<__nv_bfloat16*>(smem_raw + 3*PLANE_BYTES);
    float* btile = reinterpret_cast<float*>(smem_raw);   // union: 16 x 136 floats

    const int K = D_MODEL;
    int tid = threadIdx.x;
    int wid = tid >> 5;
    int warp_m = wid & 3;                 // 0..3 -> m offset *32
    int warp_n = wid >> 2;                // 0..1 -> n offset *64

    // Loader mapping: row = tid>>1 (0..127), k-half = (tid&1)*16
    int lrow = tid >> 1;
    int lkh  = (tid & 1) * 16;
    const float* Ap = A + (size_t)(m0 + lrow) * K + lkh;
    const float* Wp = W + (size_t)(n0 + lrow) * K + lkh;

    // Prefetch chunk 0
    float4 ar[4], wr[4];
    #pragma unroll
    for (int j = 0; j < 4; j++) {
        ar[j] = *(const float4*)(Ap + j * 4);
        wr[j] = *(const float4*)(Wp + j * 4);
    }

    // Build replicated bias tile (16 rows x 128 cols, pitch 136)
    for (int idx = tid; idx < 16 * 128; idx += 256) {
        int r = idx >> 7, c = idx & 127;
        btile[r * 136 + c] = bias[n0 + c];
    }
    __syncthreads();

    // Init accumulators from bias tile
    #pragma unroll
    for (int mt = 0; mt < 2; mt++)
        #pragma unroll
        for (int nt = 0; nt < 4; nt++)
            wmma::load_matrix_sync(acc[mt][nt],
                btile + warp_n * 64 + nt * 16, 136, wmma::mem_row_major);

    for (int k0 = 0; k0 < K; k0 += PBK) {
        __syncthreads();   // prior reads of smem done (incl. bias-frag loads)
        int sidx = lrow * PP + lkh;
        #pragma unroll
        for (int j = 0; j < 4; j++) {
            split_store(Ahi, Alo, sidx + j * 4, ar[j]);
            split_store(Bhi, Blo, sidx + j * 4, wr[j]);
        }
        __syncthreads();
        if (k0 + PBK < K) {   // prefetch next chunk
            #pragma unroll
            for (int j = 0; j < 4; j++) {
                ar[j] = *(const float4*)(Ap + k0 + PBK + j * 4);
                wr[j] = *(const float4*)(Wp + k0 + PBK + j * 4);
            }
        }
        #pragma unroll
        for (int ks = 0; ks < PBK; ks += 16) {
            FragA a_hi[2], a_lo[2];
            #pragma unroll
            for (int mt = 0; mt < 2; mt++) {
                int arow = (warp_m * 32 + mt * 16) * PP + ks;
                wmma::load_matrix_sync(a_hi[mt], Ahi + arow, PP);
                wmma::load_matrix_sync(a_lo[mt], Alo + arow, PP);
            }
            #pragma unroll
            for (int nt = 0; nt < 4; nt++) {
                FragB b_hi, b_lo;
                int brow = (warp_n * 64 + nt * 16) * PP + ks;
                wmma::load_matrix_sync(b_hi, Bhi + brow, PP);
                wmma::load_matrix_sync(b_lo, Blo + brow, PP);
                #pragma unroll
                for (int mt = 0; mt < 2; mt++) {
                    wmma::mma_sync(acc[mt][nt], a_hi[mt], b_hi, acc[mt][nt]);
                    wmma::mma_sync(acc[mt][nt], a_hi[mt], b_lo, acc[mt][nt]);
                    wmma::mma_sync(acc[mt][nt], a_lo[mt], b_hi, acc[mt][nt]);
                }
            }
        }
    }
}

// ---------------------------------------------------------------------------
// Kernel 1: fused QKV projection. grid = (8 n-tiles, 64 m-tiles, 3 [q/k/v])
// Direct wmma store into head-split layout [B, H, S, dk]: a 16-wide n-tile
// never crosses a 64-wide head; tile rows = consecutive s (ldm = 64).
// ---------------------------------------------------------------------------
__global__ void __launch_bounds__(256, 2)
qkv_proj_kernel(const float* __restrict__ q, const float* __restrict__ k_,
                const float* __restrict__ v,
                const float* __restrict__ Wq, const float* __restrict__ bq,
                const float* __restrict__ Wk, const float* __restrict__ bk,
                const float* __restrict__ Wv, const float* __restrict__ bv)
{
    __shared__ __align__(16) unsigned char smem_raw[PSM_BYTES];
    const float* A; const float* W; const float* bias; float* O;
    int z = blockIdx.z;
    if (z == 0)      { A = q;  W = Wq; bias = bq; O = g_Q; }
    else if (z == 1) { A = k_; W = Wk; bias = bk; O = g_K; }
    else             { A = v;  W = Wv; bias = bv; O = g_V; }

    int m0 = blockIdx.y * PBM;
    int n0 = blockIdx.x * 128;
    FragC acc[2][4];
    proj_gemm_core(A, W, bias, m0, n0, smem_raw, acc);

    int wid = threadIdx.x >> 5;
    int warp_m = wid & 3, warp_n = wid >> 2;
    #pragma unroll
    for (int mt = 0; mt < 2; mt++) {
        int row0 = m0 + warp_m * 32 + mt * 16;
        int b = row0 >> 11;           // / 2048
        int s0 = row0 & 2047;
        #pragma unroll
        for (int nt = 0; nt < 4; nt++) {
            int n = n0 + warp_n * 64 + nt * 16;
            int h = n >> 6, off = n & 63;
            float* dst = O + ((size_t)(b * NHEAD + h) * S_LEN + s0) * DKH + off;
            wmma::store_matrix_sync(dst, acc[mt][nt], DKH, wmma::mem_row_major);
        }
    }
}

// ---------------------------------------------------------------------------
// Kernel 2: flash-style attention (unchanged SIMT fp32 this round).
// grid = (16 q-tiles, 64 b*h), 256 threads; BQ=128, BKV=64; 80 KB dyn smem.
// ---------------------------------------------------------------------------
#define BQ  128
#define BKV 64
#define ATTN_SMEM ((DKH*BQ + BKV*DKH + BQ*BKV) * 4)   // 81920 bytes

__global__ void __launch_bounds__(256)
attn_kernel()
{
    extern __shared__ float sm[];
    float* Qs  = sm;                       // [d][q]  64 x 128
    float* KVs = sm + DKH * BQ;            // K: [d][kv] 64x64, then V: [kv][d]
    float* Ps  = sm + DKH * BQ + BKV * DKH; // [q][kv] 128 x 64

    int tid = threadIdx.x, tx = tid & 15, ty = tid >> 4;
    int bh = blockIdx.y;
    int q0 = blockIdx.x * BQ;
    const float* Qb = g_Q + (size_t)bh * S_LEN * DKH;
    const float* Kb = g_K + (size_t)bh * S_LEN * DKH;
    const float* Vb = g_V + (size_t)bh * S_LEN * DKH;

    // Load Q tile transposed into Qs[d][q]: 2048 float4s, 8 per thread
    #pragma unroll
    for (int s4 = 0; s4 < 8; s4++) {
        int sl = tid * 8 + s4;             // 0..2047
        int r  = sl >> 4;                  // 0..127
        int d4 = (sl & 15) << 2;           // 0..60
        float4 t = *(const float4*)(Qb + (size_t)(q0 + r) * DKH + d4);
        Qs[(d4+0)*BQ + r] = t.x; Qs[(d4+1)*BQ + r] = t.y;
        Qs[(d4+2)*BQ + r] = t.z; Qs[(d4+3)*BQ + r] = t.w;
    }

    float m_run[8], l_run[8], acc[8][4];
    #pragma unroll
    for (int i = 0; i < 8; i++) {
        m_run[i] = -INFINITY; l_run[i] = 0.f;
        #pragma unroll
        for (int j = 0; j < 4; j++) acc[i][j] = 0.f;
    }

    const int lr  = tid >> 2;          // 0..63: kv-row within chunk
    const int lc0 = (tid & 3) << 4;    // 0,16,32,48: dim base
    float4 kreg[4];
    #pragma unroll
    for (int j = 0; j < 4; j++)
        kreg[j] = *(const float4*)(Kb + (size_t)lr * DKH + lc0 + j * 4);

    const float SCALE = 0.125f;        // 1/sqrt(64)

    for (int c = 0; c < S_LEN / BKV; c++) {
        __syncthreads();
        #pragma unroll
        for (int j = 0; j < 4; j++) {
            int d = lc0 + j * 4;
            KVs[(d+0)*BKV + lr] = kreg[j].x;
            KVs[(d+1)*BKV + lr] = kreg[j].y;
            KVs[(d+2)*BKV + lr] = kreg[j].z;
            KVs[(d+3)*BKV + lr] = kreg[j].w;
        }
        __syncthreads();

        float4 vreg[4];
        #pragma unroll
        for (int j = 0; j < 4; j++)
            vreg[j] = *(const float4*)(Vb + (size_t)(c * BKV + lr) * DKH + lc0 + j * 4);

        // S = Q K^T  (128x64 tile, 8x4 per thread)
        float sc[8][4] = {};
        #pragma unroll 8
        for (int d = 0; d < DKH; d++) {
            float4 a0 = *(const float4*)&Qs[d * BQ + ty * 8];
            float4 a1 = *(const float4*)&Qs[d * BQ + ty * 8 + 4];
            float4 b  = *(const float4*)&KVs[d * BKV + tx * 4];
            float a[8] = {a0.x,a0.y,a0.z,a0.w,a1.x,a1.y,a1.z,a1.w};
            #pragma unroll
            for (int i = 0; i < 8; i++) {
                sc[i][0] += a[i]*b.x; sc[i][1] += a[i]*b.y;
                sc[i][2] += a[i]*b.z; sc[i][3] += a[i]*b.w;
            }
        }

        // Online softmax per row
        #pragma unroll
        for (int i = 0; i < 8; i++) {
            #pragma unroll
            for (int j = 0; j < 4; j++) sc[i][j] *= SCALE;
            float mc = fmaxf(fmaxf(sc[i][0], sc[i][1]), fmaxf(sc[i][2], sc[i][3]));
            #pragma unroll
            for (int o = 8; o > 0; o >>= 1)
                mc = fmaxf(mc, __shfl_xor_sync(0xffffffffu, mc, o));
            float mnew = fmaxf(m_run[i], mc);
            float corr = __expf(m_run[i] - mnew);
            m_run[i] = mnew;
            float ps = 0.f;
            #pragma unroll
            for (int j = 0; j < 4; j++) {
                float p = __expf(sc[i][j] - mnew);
                sc[i][j] = p; ps += p;
            }
            #pragma unroll
            for (int o = 8; o > 0; o >>= 1)
                ps += __shfl_xor_sync(0xffffffffu, ps, o);
            l_run[i] = l_run[i] * corr + ps;
            acc[i][0] *= corr; acc[i][1] *= corr;
            acc[i][2] *= corr; acc[i][3] *= corr;
        }

        __syncthreads();
        #pragma unroll
        for (int i = 0; i < 8; i++) {
            float4 p; p.x = sc[i][0]; p.y = sc[i][1]; p.z = sc[i][2]; p.w = sc[i][3];
            *(float4*)&Ps[(ty*8 + i) * BKV + tx * 4] = p;
        }
        #pragma unroll
        for (int j = 0; j < 4; j++)
            *(float4*)&KVs[lr * DKH + lc0 + j * 4] = vreg[j];
        if (c + 1 < S_LEN / BKV) {
            #pragma unroll
            for (int j = 0; j < 4; j++)
                kreg[j] = *(const float4*)(Kb + (size_t)((c + 1) * BKV + lr) * DKH + lc0 + j * 4);
        }
        __syncthreads();

        // O += P @ V
        #pragma unroll 4
        for (int kv = 0; kv < BKV; kv += 4) {
            float vv[4][4];
            #pragma unroll
            for (int r = 0; r < 4; r++) {
                float4 t = *(const float4*)&KVs[(kv + r) * DKH + tx * 4];
                vv[r][0] = t.x; vv[r][1] = t.y; vv[r][2] = t.z; vv[r][3] = t.w;
            }
            #pragma unroll
            for (int i = 0; i < 8; i++) {
                float4 p = *(const float4*)&Ps[(ty*8 + i) * BKV + kv];
                float pr[4] = {p.x, p.y, p.z, p.w};
                #pragma unroll
                for (int r = 0; r < 4; r++) {
                    acc[i][0] += pr[r] * vv[r][0];
                    acc[i][1] += pr[r] * vv[r][1];
                    acc[i][2] += pr[r] * vv[r][2];
                    acc[i][3] += pr[r] * vv[r][3];
                }
            }
        }
    }

    // Normalize and store into [B, S, H*dk] (= merged-head) layout
    int b = bh >> 4, h = bh & 15;
    #pragma unroll
    for (int i = 0; i < 8; i++) {
        float inv = 1.0f / l_run[i];
        int s = q0 + ty * 8 + i;
        float4 o;
        o.x = acc[i][0] * inv; o.y = acc[i][1] * inv;
        o.z = acc[i][2] * inv; o.w = acc[i][3] * inv;
        *(float4*)(g_ctx + (size_t)(b * S_LEN + s) * D_MODEL + h * DKH + tx * 4) = o;
    }
}

// ---------------------------------------------------------------------------
// Kernel 3: output projection  out = ctx @ Wo^T + bo  (wmma bf16 split)
// ---------------------------------------------------------------------------
__global__ void __launch_bounds__(256, 2)
out_proj_kernel(const float* __restrict__ Wo, const float* __restrict__ bo,
                float* __restrict__ out)
{
    __shared__ __align__(16) unsigned char smem_raw[PSM_BYTES];
    int m0 = blockIdx.y * PBM;
    int n0 = blockIdx.x * 128;
    FragC acc[2][4];
    proj_gemm_core(g_ctx, Wo, bo, m0, n0, smem_raw, acc);

    int wid = threadIdx.x >> 5;
    int warp_m = wid & 3, warp_n = wid >> 2;
    #pragma unroll
    for (int mt = 0; mt < 2; mt++) {
        int row0 = m0 + warp_m * 32 + mt * 16;
        #pragma unroll
        for (int nt = 0; nt < 4; nt++) {
            int n = n0 + warp_n * 64 + nt * 16;
            wmma::store_matrix_sync(out + (size_t)row0 * D_MODEL + n,
                                    acc[mt][nt], D_MODEL, wmma::mem_row_major);
        }
    }
}

// ---------------------------------------------------------------------------
// Launch. Input order (metadata): q,k,v,Wq,bq,Wk,bk,Wv,bv,Wo,bo
// ---------------------------------------------------------------------------
extern "C" void kernel_launch(void* const* d_in, const int* in_sizes, int n_in,
                              void* d_out, int out_size)
{
    const float* q  = (const float*)d_in[0];
    const float* k  = (const float*)d_in[1];
    const float* v  = (const float*)d_in[2];
    const float* Wq = (const float*)d_in[3];
    const float* bq = (const float*)d_in[4];
    const float* Wk = (const float*)d_in[5];
    const float* bk = (const float*)d_in[6];
    const float* Wv = (const float*)d_in[7];
    const float* bv = (const float*)d_in[8];
    const float* Wo = (const float*)d_in[9];
    const float* bo = (const float*)d_in[10];
    float* out = (float*)d_out;

    // Idempotent, host-side, capture-safe: allow 80 KB dynamic smem for attn
    cudaFuncSetAttribute(attn_kernel,
                         cudaFuncAttributeMaxDynamicSharedMemorySize, ATTN_SMEM);

    dim3 blk(256);
    qkv_proj_kernel<<<dim3(D_MODEL / 128, ROWS / PBM, 3), blk>>>(
        q, k, v, Wq, bq, Wk, bk, Wv, bv);
    attn_kernel<<<dim3(S_LEN / BQ, BATCH * NHEAD), blk, ATTN_SMEM>>>();
    out_proj_kernel<<<dim3(D_MODEL / 128, ROWS / PBM), blk>>>(Wo, bo, out);
}

// round 11
// speedup vs baseline: 1.7488x; 1.1751x over previous
#include <cuda_runtime.h>
#include <cuda_bf16.h>
#include <mma.h>
#include <math.h>

using namespace nvcuda;

// Problem constants
#define D_MODEL 1024
#define NHEAD   16
#define DKH     64
#define S_LEN   2048
#define BATCH   4
#define ROWS    (BATCH * S_LEN)   // 8192

// Scratch (static device globals: allocation-free per harness rules)
__device__ float g_Q[ROWS * D_MODEL];
__device__ float g_K[ROWS * D_MODEL];
__device__ float g_V[ROWS * D_MODEL];
__device__ float g_ctx[ROWS * D_MODEL];

// ---------------------------------------------------------------------------
// Shared helpers: fp32 -> (bf16 hi, bf16 lo) split
// ---------------------------------------------------------------------------
__device__ __forceinline__ void split_store(__nv_bfloat16* hi, __nv_bfloat16* lo,
                                            int idx, float4 v)
{
    float f[4] = {v.x, v.y, v.z, v.w};
    __nv_bfloat16 h[4], l[4];
    #pragma unroll
    for (int e = 0; e < 4; e++) {
        h[e] = __float2bfloat16_rn(f[e]);
        l[e] = __float2bfloat16_rn(f[e] - __bfloat162float(h[e]));
    }
    *reinterpret_cast<__nv_bfloat162*>(hi + idx)     = __nv_bfloat162(h[0], h[1]);
    *reinterpret_cast<__nv_bfloat162*>(hi + idx + 2) = __nv_bfloat162(h[2], h[3]);
    *reinterpret_cast<__nv_bfloat162*>(lo + idx)     = __nv_bfloat162(l[0], l[1]);
    *reinterpret_cast<__nv_bfloat162*>(lo + idx + 2) = __nv_bfloat162(l[2], l[3]);
}

typedef wmma::fragment<wmma::matrix_a, 16,16,16, __nv_bfloat16, wmma::row_major> FragA;
typedef wmma::fragment<wmma::matrix_b, 16,16,16, __nv_bfloat16, wmma::col_major> FragBc;
typedef wmma::fragment<wmma::matrix_b, 16,16,16, __nv_bfloat16, wmma::row_major> FragBr;
typedef wmma::fragment<wmma::accumulator, 16,16,16, float> FragC;

// ---------------------------------------------------------------------------
// Projection GEMM via wmma bf16 split:  C = A @ W^T + bias
// ---------------------------------------------------------------------------
#define PBM 128
#define PBK 32
#define PP  40
#define PLANE_BYTES (PBM * PP * 2)
#define PSM_BYTES   (4 * PLANE_BYTES)

__device__ __forceinline__ void proj_gemm_core(
    const float* __restrict__ A, const float* __restrict__ W,
    const float* __restrict__ bias, int m0, int n0,
    unsigned char* smem_raw, FragC (&acc)[2][4])
{
    __nv_bfloat16* Ahi = reinterpret_cast<__nv_bfloat16*>(smem_raw);
    __nv_bfloat16* Alo = reinterpret_cast<__nv_bfloat16*>(smem_raw + PLANE_BYTES);
    __nv_bfloat16* Bhi = reinterpret_cast<__nv_bfloat16*>(smem_raw + 2*PLANE_BYTES);
    __nv_bfloat16* Blo = reinterpret_cast<__nv_bfloat16*>(smem_raw + 3*PLANE_BYTES);
    float* btile = reinterpret_cast<float*>(smem_raw);

    const int K = D_MODEL;
    int tid = threadIdx.x;
    int wid = tid >> 5;
    int warp_m = wid & 3;
    int warp_n = wid >> 2;

    int lrow = tid >> 1;
    int lkh  = (tid & 1) * 16;
    const float* Ap = A + (size_t)(m0 + lrow) * K + lkh;
    const float* Wp = W + (size_t)(n0 + lrow) * K + lkh;

    float4 ar[4], wr[4];
    #pragma unroll
    for (int j = 0; j < 4; j++) {
        ar[j] = *(const float4*)(Ap + j * 4);
        wr[j] = *(const float4*)(Wp + j * 4);
    }

    for (int idx = tid; idx < 16 * 128; idx += 256) {
        int r = idx >> 7, c = idx & 127;
        btile[r * 136 + c] = bias[n0 + c];
    }
    __syncthreads();

    #pragma unroll
    for (int mt = 0; mt < 2; mt++)
        #pragma unroll
        for (int nt = 0; nt < 4; nt++)
            wmma::load_matrix_sync(acc[mt][nt],
                btile + warp_n * 64 + nt * 16, 136, wmma::mem_row_major);

    for (int k0 = 0; k0 < K; k0 += PBK) {
        __syncthreads();
        int sidx = lrow * PP + lkh;
        #pragma unroll
        for (int j = 0; j < 4; j++) {
            split_store(Ahi, Alo, sidx + j * 4, ar[j]);
            split_store(Bhi, Blo, sidx + j * 4, wr[j]);
        }
        __syncthreads();
        if (k0 + PBK < K) {
            #pragma unroll
            for (int j = 0; j < 4; j++) {
                ar[j] = *(const float4*)(Ap + k0 + PBK + j * 4);
                wr[j] = *(const float4*)(Wp + k0 + PBK + j * 4);
            }
        }
        #pragma unroll
        for (int ks = 0; ks < PBK; ks += 16) {
            FragA a_hi[2], a_lo[2];
            #pragma unroll
            for (int mt = 0; mt < 2; mt++) {
                int arow = (warp_m * 32 + mt * 16) * PP + ks;
                wmma::load_matrix_sync(a_hi[mt], Ahi + arow, PP);
                wmma::load_matrix_sync(a_lo[mt], Alo + arow, PP);
            }
            #pragma unroll
            for (int nt = 0; nt < 4; nt++) {
                FragBc b_hi, b_lo;
                int brow = (warp_n * 64 + nt * 16) * PP + ks;
                wmma::load_matrix_sync(b_hi, Bhi + brow, PP);
                wmma::load_matrix_sync(b_lo, Blo + brow, PP);
                #pragma unroll
                for (int mt = 0; mt < 2; mt++) {
                    wmma::mma_sync(acc[mt][nt], a_hi[mt], b_hi, acc[mt][nt]);
                    wmma::mma_sync(acc[mt][nt], a_hi[mt], b_lo, acc[mt][nt]);
                    wmma::mma_sync(acc[mt][nt], a_lo[mt], b_hi, acc[mt][nt]);
                }
            }
        }
    }
}

// Kernel 1: fused QKV projection -> head-split layout [B, H, S, dk]
__global__ void __launch_bounds__(256, 2)
qkv_proj_kernel(const float* __restrict__ q, const float* __restrict__ k_,
                const float* __restrict__ v,
                const float* __restrict__ Wq, const float* __restrict__ bq,
                const float* __restrict__ Wk, const float* __restrict__ bk,
                const float* __restrict__ Wv, const float* __restrict__ bv)
{
    __shared__ __align__(16) unsigned char smem_raw[PSM_BYTES];
    const float* A; const float* W; const float* bias; float* O;
    int z = blockIdx.z;
    if (z == 0)      { A = q;  W = Wq; bias = bq; O = g_Q; }
    else if (z == 1) { A = k_; W = Wk; bias = bk; O = g_K; }
    else             { A = v;  W = Wv; bias = bv; O = g_V; }

    int m0 = blockIdx.y * PBM;
    int n0 = blockIdx.x * 128;
    FragC acc[2][4];
    proj_gemm_core(A, W, bias, m0, n0, smem_raw, acc);

    int wid = threadIdx.x >> 5;
    int warp_m = wid & 3, warp_n = wid >> 2;
    #pragma unroll
    for (int mt = 0; mt < 2; mt++) {
        int row0 = m0 + warp_m * 32 + mt * 16;
        int b = row0 >> 11;
        int s0 = row0 & 2047;
        #pragma unroll
        for (int nt = 0; nt < 4; nt++) {
            int n = n0 + warp_n * 64 + nt * 16;
            int h = n >> 6, off = n & 63;
            float* dst = O + ((size_t)(b * NHEAD + h) * S_LEN + s0) * DKH + off;
            wmma::store_matrix_sync(dst, acc[mt][nt], DKH, wmma::mem_row_major);
        }
    }
}

// ---------------------------------------------------------------------------
// Kernel 2: tensor-core flash attention.
// grid = (16 q-tiles, 64 b*h), 256 threads (8 warps); BQ=128, BKV=64.
// Smem: Q hi/lo [128][72], K/V hi/lo [64][72], O fp32 [128][68],
//       S fp32 [128][68] unioned with P hi/lo [128][72]. Total 126976 B.
// S = Q K^T via wmma (B col-major over [kv][d]); SIMT online softmax on S;
// O kept in smem fp32 (per-row rescale SIMT-side); PV via wmma (B row-major).
// ---------------------------------------------------------------------------
#define BQ  128
#define BKV 64
#define BP  72     // bf16 plane pitch
#define FP  68     // fp32 pitch
#define Q_PLANE  (BQ * BP)    // 9216
#define KV_PLANE (BKV * BP)   // 4608
#define O_ELEMS  (BQ * FP)    // 8704
#define ATTN_SMEM (2*Q_PLANE*2 + 2*KV_PLANE*2 + O_ELEMS*4 + 2*Q_PLANE*2) // 126976

__global__ void __launch_bounds__(256)
attn_kernel()
{
    extern __shared__ __align__(16) unsigned char smraw[];
    __nv_bfloat16* Qhi = reinterpret_cast<__nv_bfloat16*>(smraw);
    __nv_bfloat16* Qlo = Qhi + Q_PLANE;
    __nv_bfloat16* Khi = Qlo + Q_PLANE;
    __nv_bfloat16* Klo = Khi + KV_PLANE;
    float* Osm = reinterpret_cast<float*>(Klo + KV_PLANE);
    float* Ssm = Osm + O_ELEMS;
    __nv_bfloat16* Phi = reinterpret_cast<__nv_bfloat16*>(Ssm);
    __nv_bfloat16* Plo = Phi + Q_PLANE;

    int tid = threadIdx.x;
    int wid = tid >> 5;
    int bh = blockIdx.y;
    int q0 = blockIdx.x * BQ;
    const float* Qb = g_Q + (size_t)bh * S_LEN * DKH;
    const float* Kb = g_K + (size_t)bh * S_LEN * DKH;
    const float* Vb = g_V + (size_t)bh * S_LEN * DKH;

    // Per-thread row ownership for SIMT phases
    const int r  = tid >> 1;            // 0..127
    const int c0 = (tid & 1) * 32;      // 0 or 32

    // Load + split Q tile once: row r, cols c0..c0+31 (8 float4)
    #pragma unroll
    for (int j = 0; j < 8; j++) {
        float4 t = *(const float4*)(Qb + (size_t)(q0 + r) * DKH + c0 + j * 4);
        split_store(Qhi, Qlo, r * BP + c0 + j * 4, t);
    }
    // Zero O
    for (int i = tid; i < O_ELEMS; i += 256)Osm[i] = 0.f;

    float m_run = -INFINITY, l_run = 0.f;

    // KV loader mapping (full 64x64 coverage)
    const int lr  = tid >> 2;
    const int lc0 = (tid & 3) << 4;
    float4 kreg[4];
    #pragma unroll
    for (int j = 0; j < 4; j++)
        kreg[j] = *(const float4*)(Kb + (size_t)lr * DKH + lc0 + j * 4);

    const float SCALE = 0.125f;   // 1/sqrt(64)

    for (int c = 0; c < S_LEN / BKV; c++) {
        __syncthreads();                    // (1) prev PV done with V planes / Osm
        #pragma unroll
        for (int j = 0; j < 4; j++)
            split_store(Khi, Klo, lr * BP + lc0 + j * 4, kreg[j]);
        __syncthreads();                    // (2) K planes ready

        // Prefetch V (overlaps S MMAs)
        float4 vreg[4];
        #pragma unroll
        for (int j = 0; j < 4; j++)
            vreg[j] = *(const float4*)(Vb + (size_t)(c * BKV + lr) * DKH + lc0 + j * 4);

        // ---- S = Q K^T : warp wid owns rows wid*16..+15, all 64 kv cols ----
        {
            FragC sf[4];
            #pragma unroll
            for (int nt = 0; nt < 4; nt++) wmma::fill_fragment(sf[nt], 0.0f);
            #pragma unroll
            for (int ks = 0; ks < 4; ks++) {
                FragA ah, al;
                wmma::load_matrix_sync(ah, Qhi + (wid * 16) * BP + ks * 16, BP);
                wmma::load_matrix_sync(al, Qlo + (wid * 16) * BP + ks * 16, BP);
                #pragma unroll
                for (int nt = 0; nt < 4; nt++) {
                    FragBc bh_, bl_;
                    wmma::load_matrix_sync(bh_, Khi + (nt * 16) * BP + ks * 16, BP);
                    wmma::load_matrix_sync(bl_, Klo + (nt * 16) * BP + ks * 16, BP);
                    wmma::mma_sync(sf[nt], ah, bh_, sf[nt]);
                    wmma::mma_sync(sf[nt], ah, bl_, sf[nt]);
                    wmma::mma_sync(sf[nt], al, bh_, sf[nt]);
                }
            }
            #pragma unroll
            for (int nt = 0; nt < 4; nt++)
                wmma::store_matrix_sync(Ssm + (wid * 16) * FP + nt * 16, sf[nt],
                                        FP, wmma::mem_row_major);
        }
        __syncthreads();                    // (3) S ready

        // Prefetch next K (overlaps softmax)
        if (c + 1 < S_LEN / BKV) {
            #pragma unroll
            for (int j = 0; j < 4; j++)
                kreg[j] = *(const float4*)(Kb + (size_t)((c + 1) * BKV + lr) * DKH + lc0 + j * 4);
        }

        // ---- SIMT online softmax: thread owns row r, cols c0..c0+31 ----
        float p[32];
        float corr;
        {
            float s[32];
            #pragma unroll
            for (int j = 0; j < 8; j++) {
                float4 t = *(const float4*)&Ssm[r * FP + c0 + j * 4];
                s[j*4+0] = t.x * SCALE; s[j*4+1] = t.y * SCALE;
                s[j*4+2] = t.z * SCALE; s[j*4+3] = t.w * SCALE;
            }
            float mc = s[0];
            #pragma unroll
            for (int j = 1; j < 32; j++) mc = fmaxf(mc, s[j]);
            mc = fmaxf(mc, __shfl_xor_sync(0xffffffffu, mc, 1));
            float mnew = fmaxf(m_run, mc);
            corr = __expf(m_run - mnew);
            m_run = mnew;
            float ps = 0.f;
            #pragma unroll
            for (int j = 0; j < 32; j++) {
                p[j] = __expf(s[j] - mnew);
                ps += p[j];
            }
            ps += __shfl_xor_sync(0xffffffffu, ps, 1);
            l_run = l_run * corr + ps;
        }
        __syncthreads();                    // (4) all S reads done; P may overwrite

        // Write P hi/lo; rescale own O row slice; store V split into K planes
        {
            __nv_bfloat16 hb[32], lb[32];
            #pragma unroll
            for (int j = 0; j < 32; j++) {
                hb[j] = __float2bfloat16_rn(p[j]);
                lb[j] = __float2bfloat16_rn(p[j] - __bfloat162float(hb[j]));
            }
            float4* Ph4 = reinterpret_cast<float4*>(Phi + r * BP + c0);
            float4* Pl4 = reinterpret_cast<float4*>(Plo + r * BP + c0);
            const float4* hb4 = reinterpret_cast<const float4*>(hb);
            const float4* lb4 = reinterpret_cast<const float4*>(lb);
            #pragma unroll
            for (int j = 0; j < 4; j++) { Ph4[j] = hb4[j]; Pl4[j] = lb4[j]; }

            #pragma unroll
            for (int j = 0; j < 8; j++) {
                float4* o4 = reinterpret_cast<float4*>(&Osm[r * FP + c0 + j * 4]);
                float4 t = *o4;
                t.x *= corr; t.y *= corr; t.z *= corr; t.w *= corr;
                *o4 = t;
            }
            #pragma unroll
            for (int j = 0; j < 4; j++)
                split_store(Khi, Klo, lr * BP + lc0 + j * 4, vreg[j]);
        }
        __syncthreads();                    // (5) P, rescaled O, V planes ready

        // ---- O += P V : warp wid owns rows wid*16..+15, all 64 d cols ----
        {
            FragC of[4];
            #pragma unroll
            for (int nt = 0; nt < 4; nt++)
                wmma::load_matrix_sync(of[nt], Osm + (wid * 16) * FP + nt * 16,
                                       FP, wmma::mem_row_major);
            #pragma unroll
            for (int ks = 0; ks < 4; ks++) {
                FragA ph_, pl_;
                wmma::load_matrix_sync(ph_, Phi + (wid * 16) * BP + ks * 16, BP);
                wmma::load_matrix_sync(pl_, Plo + (wid * 16) * BP + ks * 16, BP);
                #pragma unroll
                for (int nt = 0; nt < 4; nt++) {
                    FragBr vh_, vl_;
                    wmma::load_matrix_sync(vh_, Khi + (ks * 16) * BP + nt * 16, BP);
                    wmma::load_matrix_sync(vl_, Klo + (ks * 16) * BP + nt * 16, BP);
                    wmma::mma_sync(of[nt], ph_, vh_, of[nt]);
                    wmma::mma_sync(of[nt], ph_, vl_, of[nt]);
                    wmma::mma_sync(of[nt], pl_, vh_, of[nt]);
                }
            }
            #pragma unroll
            for (int nt = 0; nt < 4; nt++)
                wmma::store_matrix_sync(Osm + (wid * 16) * FP + nt * 16, of[nt],
                                        FP, wmma::mem_row_major);
        }
    }
    __syncthreads();

    // Normalize own row slice, store to merged-head layout [B, S, H*dk]
    int b = bh >> 4, h = bh & 15;
    float inv = 1.0f / l_run;
    int s = q0 + r;
    float* dst = g_ctx + (size_t)(b * S_LEN + s) * D_MODEL + h * DKH + c0;
    #pragma unroll
    for (int j = 0; j < 8; j++) {
        float4 t = *(const float4*)&Osm[r * FP + c0 + j * 4];
        t.x *= inv; t.y *= inv; t.z *= inv; t.w *= inv;
        *(float4*)(dst + j * 4) = t;
    }
}

// ---------------------------------------------------------------------------
// Kernel 3: output projection  out = ctx @ Wo^T + bo  (wmma bf16 split)
// ---------------------------------------------------------------------------
__global__ void __launch_bounds__(256, 2)
out_proj_kernel(const float* __restrict__ Wo, const float* __restrict__ bo,
                float* __restrict__ out)
{
    __shared__ __align__(16) unsigned char smem_raw[PSM_BYTES];
    int m0 = blockIdx.y * PBM;
    int n0 = blockIdx.x * 128;
    FragC acc[2][4];
    proj_gemm_core(g_ctx, Wo, bo, m0, n0, smem_raw, acc);

    int wid = threadIdx.x >> 5;
    int warp_m = wid & 3, warp_n = wid >> 2;
    #pragma unroll
    for (int mt = 0; mt < 2; mt++) {
        int row0 = m0 + warp_m * 32 + mt * 16;
        #pragma unroll
        for (int nt = 0; nt < 4; nt++) {
            int n = n0 + warp_n * 64 + nt * 16;
            wmma::store_matrix_sync(out + (size_t)row0 * D_MODEL + n,
                                    acc[mt][nt], D_MODEL, wmma::mem_row_major);
        }
    }
}

// ---------------------------------------------------------------------------
// Launch. Input order (metadata): q,k,v,Wq,bq,Wk,bk,Wv,bv,Wo,bo
// ---------------------------------------------------------------------------
extern "C" void kernel_launch(void* const* d_in, const int* in_sizes, int n_in,
                              void* d_out, int out_size)
{
    const float* q  = (const float*)d_in[0];
    const float* k  = (const float*)d_in[1];
    const float* v  = (const float*)d_in[2];
    const float* Wq = (const float*)d_in[3];
    const float* bq = (const float*)d_in[4];
    const float* Wk = (const float*)d_in[5];
    const float* bk = (const float*)d_in[6];
    const float* Wv = (const float*)d_in[7];
    const float* bv = (const float*)d_in[8];
    const float* Wo = (const float*)d_in[9];
    const float* bo = (const float*)d_in[10];
    float* out = (float*)d_out;

    // Idempotent, host-side, capture-safe
    cudaFuncSetAttribute(attn_kernel,
                         cudaFuncAttributeMaxDynamicSharedMemorySize, ATTN_SMEM);

    dim3 blk(256);
    qkv_proj_kernel<<<dim3(D_MODEL / 128, ROWS / PBM, 3), blk>>>(
        q, k, v, Wq, bq, Wk, bk, Wv, bv);
    attn_kernel<<<dim3(S_LEN / BQ, BATCH * NHEAD), blk, ATTN_SMEM>>>();
    out_proj_kernel<<<dim3(D_MODEL / 128, ROWS / PBM), blk>>>(Wo, bo, out);
}